// round 15
// baseline (speedup 1.0000x reference)
#include <cuda_runtime.h>
#include <cuda_fp16.h>
#include <cstdint>

// ---------------- problem constants ----------------
#define Bc 8
#define Tc 16
#define Nn 1024
#define FIN 32
#define FOUT 64
#define Kc 3
#define CC 512
#define NN (1024 * 1024)

// ---------------- scratch (no cudaMalloc allowed) ----------------
__device__ __half g_att[(size_t)Bc * Kc * NN];         // fp16(cheb*sa) [bk][i][j]  (50 MB)
__device__ __half g_xh[(size_t)Bc * CC * Nn];          // x^T fp16 [b][c][j]         (8 MB)
__device__ __half g_rhsh[(size_t)Bc * Kc * Nn * CC];   // fp16 rhs [bk][i][c]        (25 MB)
__device__ __half g_tht[FOUT * 96];                    // Theta^T fp16 [o][m]

// ---------------- helpers ----------------
__device__ __forceinline__ uint32_t smem_u32(const void* p) {
    uint32_t a;
    asm("{ .reg .u64 t; cvta.to.shared.u64 t, %1; cvt.u32.u64 %0, t; }" : "=r"(a) : "l"(p));
    return a;
}

__device__ __forceinline__ uint32_t pack2h(float a, float b) {
    __half ha = __float2half_rn(a);
    __half hb = __float2half_rn(b);
    return (uint32_t)__half_as_ushort(ha) | ((uint32_t)__half_as_ushort(hb) << 16);
}

__device__ __forceinline__ void mma16816(float* d, const uint32_t* a, uint32_t b0, uint32_t b1) {
    asm volatile(
        "mma.sync.aligned.m16n8k16.row.col.f32.f16.f16.f32 "
        "{%0,%1,%2,%3}, {%4,%5,%6,%7}, {%8,%9}, {%0,%1,%2,%3};"
        : "+f"(d[0]), "+f"(d[1]), "+f"(d[2]), "+f"(d[3])
        : "r"(a[0]), "r"(a[1]), "r"(a[2]), "r"(a[3]), "r"(b0), "r"(b1));
}

#define LDMATRIX_X4(r, addr) \
    asm volatile("ldmatrix.sync.aligned.m8n8.x4.shared.b16 {%0,%1,%2,%3}, [%4];" \
        : "=r"((r)[0]), "=r"((r)[1]), "=r"((r)[2]), "=r"((r)[3]) : "r"(addr))

#define CP_ASYNC16(dst_u32, src_ptr) \
    asm volatile("cp.async.cg.shared.global [%0], [%1], 16;" :: "r"(dst_u32), "l"(src_ptr))
#define CP_ASYNC_COMMIT() asm volatile("cp.async.commit_group;" ::: "memory")
#define CP_ASYNC_WAIT0()  asm volatile("cp.async.wait_group 0;" ::: "memory")

// ---------------------------------------------------------------------------
// Kernel 0 (merged prep):
//   blocks [0, 2048): att = fp16(cheb*sa); 8 positions x 2 b x 3 k per thread
//   blocks [2048, 3072): x transpose -> xT fp16 [b, c=t*32+f, j]
//   block 3072: ThT[o][m] = fp16(Theta[m][o])
// ---------------------------------------------------------------------------
#define ATT_BLKS 2048                    // (NN/8/256) * 4 b-pairs
#define X_BLKS   1024
#define PREP_GRID (ATT_BLKS + X_BLKS + 1)

__global__ __launch_bounds__(256)
void k_prep_all(const float* __restrict__ cheb, const float* __restrict__ sa,
                const float* __restrict__ x, const float* __restrict__ Theta) {
    __shared__ float tile[128][33];
    const int bid = blockIdx.x;
    const int tid = threadIdx.x;

    if (bid < ATT_BLKS) {
        const int bpair = bid & 3;                      // 0..3 -> b in {2p, 2p+1}
        const int pos = ((bid >> 2) * 256 + tid) * 8;   // 8 consecutive floats
        // cheb for all 3 k (L2-resident; re-read per b-pair)
        float4 c0[3], c1[3];
        #pragma unroll
        for (int k = 0; k < 3; k++) {
            c0[k] = *(const float4*)(cheb + (size_t)k * NN + pos);
            c1[k] = *(const float4*)(cheb + (size_t)k * NN + pos + 4);
        }
        #pragma unroll
        for (int q = 0; q < 2; q++) {
            int b = bpair * 2 + q;
            float4 s0 = *(const float4*)(sa + (size_t)b * NN + pos);
            float4 s1 = *(const float4*)(sa + (size_t)b * NN + pos + 4);
            #pragma unroll
            for (int k = 0; k < 3; k++) {
                uint4 w;
                w.x = pack2h(c0[k].x * s0.x, c0[k].y * s0.y);
                w.y = pack2h(c0[k].z * s0.z, c0[k].w * s0.w);
                w.z = pack2h(c1[k].x * s1.x, c1[k].y * s1.y);
                w.w = pack2h(c1[k].z * s1.z, c1[k].w * s1.w);
                *(uint4*)(g_att + (size_t)(b * 3 + k) * NN + pos) = w;
            }
        }
    } else if (bid < ATT_BLKS + X_BLKS) {
        const int blk = bid - ATT_BLKS;
        const int jc = blk & 7;
        const int t  = (blk >> 3) & 15;
        const int b  = blk >> 7;
        const int j0 = jc * 128;

        const float* src = x + (((size_t)b * Tc + t) * Nn + j0) * FIN;
        #pragma unroll
        for (int e = 0; e < 4; e++) {
            int li = e * 256 + tid;
            int row = li >> 3, q = li & 7;
            float4 v = ((const float4*)src)[li];
            tile[row][q * 4 + 0] = v.x;
            tile[row][q * 4 + 1] = v.y;
            tile[row][q * 4 + 2] = v.z;
            tile[row][q * 4 + 3] = v.w;
        }
        __syncthreads();
        #pragma unroll
        for (int e = 0; e < 8; e++) {
            int li = e * 256 + tid;
            int f = li >> 6, jp = li & 63;
            int jj = jp * 2;
            uint32_t w = pack2h(tile[jj][f], tile[jj + 1][f]);
            size_t off = ((size_t)b * CC + t * FIN + f) * Nn + j0 + jj;
            *(uint32_t*)((char*)g_xh + off * 2) = w;
        }
    } else {
        for (int idx = tid; idx < 96 * FOUT; idx += 256) {
            int m = idx / FOUT, o = idx % FOUT;
            g_tht[o * 96 + m] = __float2half_rn(Theta[idx]);
        }
    }
}

// ---------------------------------------------------------------------------
// Kernel 1: GEMM rhs[bk,i,c] = sum_j att[bk,i,j] * x[b,c,j]   (1-term fp16)
// CTA 128(M) x 128(N), BK=64, double-buffered, 256 threads,
// 8 warps 2(M) x 4(N), warp tile 64x32. 2 CTAs/SM.   [exact R8/R12/R13]
// ---------------------------------------------------------------------------
#define BKg 64
#define NSTG 16
#define PITCH 144
#define OFF_A  0
#define A_SZ   (128 * PITCH)
#define OFF_B  A_SZ
#define B_SZ   (128 * PITCH)
#define STG_SZ (A_SZ + B_SZ)
#define GEMM_SMEM (2 * STG_SZ)          // 73728

__device__ __forceinline__ void cp_stage(uint32_t sstage, const __half* __restrict__ Ap,
                                         const __half* __restrict__ Bp, int j0, int tid) {
    #pragma unroll
    for (int e = 0; e < 4; e++) {
        int li = tid + e * 256;
        int row = li >> 3, q = li & 7;
        CP_ASYNC16(sstage + OFF_A + row * PITCH + q * 16,
                   (const char*)(Ap + (size_t)row * Nn + j0) + q * 16);
    }
    #pragma unroll
    for (int e = 0; e < 4; e++) {
        int li = tid + e * 256;
        int n = li >> 3, q = li & 7;
        CP_ASYNC16(sstage + OFF_B + n * PITCH + q * 16,
                   (const char*)(Bp + (size_t)n * Nn + j0) + q * 16);
    }
}

__global__ __launch_bounds__(256, 2)
void k_gemm_mma(int dummy) {
    extern __shared__ char smem[];
    const uint32_t sb = smem_u32(smem);
    const int tid = threadIdx.x;
    const int lane = tid & 31, wid = tid >> 5;
    const int wm = wid >> 2, wn = wid & 3;

    const int tile_c = blockIdx.x * 128;
    const int tile_i = blockIdx.y * 128;
    const int bk = blockIdx.z;
    const int b = bk / 3;

    const __half* Ap = g_att + (size_t)bk * NN + (size_t)tile_i * Nn;
    const __half* Bp = g_xh + ((size_t)b * CC + tile_c) * Nn;

    float acc[4][4][4];
    #pragma unroll
    for (int m = 0; m < 4; m++)
        #pragma unroll
        for (int n = 0; n < 4; n++)
            #pragma unroll
            for (int r = 0; r < 4; r++) acc[m][n][r] = 0.f;

    const uint32_t a_off = wm * 64 * PITCH + (lane & 15) * PITCH + (lane >> 4) * 16;
    const uint32_t b_off = (wn * 32 + (lane & 7) + ((lane >> 4) << 3)) * PITCH
                         + ((lane >> 3) & 1) * 16;

    cp_stage(sb, Ap, Bp, 0, tid);
    CP_ASYNC_COMMIT();

    #pragma unroll 1
    for (int s = 0; s < NSTG; s++) {
        const uint32_t sbs = sb + (s & 1) * STG_SZ;

        CP_ASYNC_WAIT0();
        __syncthreads();

        if (s + 1 < NSTG) {
            cp_stage(sb + ((s + 1) & 1) * STG_SZ, Ap, Bp, (s + 1) * BKg, tid);
            CP_ASYNC_COMMIT();
        }

        #pragma unroll
        for (int ks = 0; ks < 4; ks++) {
            uint32_t af[4][4], bf[2][4];
            #pragma unroll
            for (int mt = 0; mt < 4; mt++)
                LDMATRIX_X4(af[mt], sbs + OFF_A + a_off + mt * 16 * PITCH + ks * 32);
            #pragma unroll
            for (int ng = 0; ng < 2; ng++)
                LDMATRIX_X4(bf[ng], sbs + OFF_B + b_off + ng * 16 * PITCH + ks * 32);
            #pragma unroll
            for (int mt = 0; mt < 4; mt++)
                #pragma unroll
                for (int ng = 0; ng < 2; ng++) {
                    mma16816(acc[mt][2 * ng],     af[mt], bf[ng][0], bf[ng][1]);
                    mma16816(acc[mt][2 * ng + 1], af[mt], bf[ng][2], bf[ng][3]);
                }
        }
    }

    __half* Cb = g_rhsh + (size_t)bk * Nn * CC;
    #pragma unroll
    for (int mt = 0; mt < 4; mt++) {
        int r0 = tile_i + wm * 64 + mt * 16 + (lane >> 2);
        #pragma unroll
        for (int nt = 0; nt < 4; nt++) {
            int c0 = tile_c + wn * 32 + nt * 8 + (lane & 3) * 2;
            *(uint32_t*)(Cb + (size_t)r0 * CC + c0)       = pack2h(acc[mt][nt][0], acc[mt][nt][1]);
            *(uint32_t*)(Cb + (size_t)(r0 + 8) * CC + c0) = pack2h(acc[mt][nt][2], acc[mt][nt][3]);
        }
    }
}

// ---------------------------------------------------------------------------
// Kernel 2: tensor-core projection + ReLU   [exact R8/R12/R13]
// CTA: 16 i x 16 t = 256 rows, K=96, N=64. 8 warps 4(M)x2(N).
// ---------------------------------------------------------------------------
#define P_PITCH 208
#define P_A_SZ  (256 * P_PITCH)
#define P_B_OFF P_A_SZ
#define PROJ_SMEM (P_A_SZ + 64 * P_PITCH)   // 66560

__global__ __launch_bounds__(256, 2)
void k_proj_mma(float* __restrict__ out) {
    extern __shared__ char smem[];
    const uint32_t sb = smem_u32(smem);
    const int tid = threadIdx.x;
    const int lane = tid & 31, wid = tid >> 5;
    const int wm = wid >> 1, wn = wid & 1;

    const int b  = blockIdx.y;
    const int i0 = blockIdx.x * 16;

    #pragma unroll
    for (int e = 0; e < 12; e++) {
        int li = tid + e * 256;
        int k = li >> 10;
        int rem = li & 1023;
        int il = rem >> 6, q = rem & 63;
        int t = q >> 2, fq = q & 3;
        const char* src = (const char*)(g_rhsh + ((size_t)(b * 3 + k) * Nn + i0 + il) * CC) + q * 16;
        CP_ASYNC16(sb + (il * 16 + t) * P_PITCH + k * 64 + fq * 16, src);
    }
    #pragma unroll
    for (int e = 0; e < 3; e++) {
        int li = tid + e * 256;
        int row = li / 12, q = li % 12;
        CP_ASYNC16(sb + P_B_OFF + row * P_PITCH + q * 16,
                   (const char*)(g_tht + row * 96) + q * 16);
    }
    CP_ASYNC_COMMIT();
    CP_ASYNC_WAIT0();
    __syncthreads();

    float acc[4][4][4];
    #pragma unroll
    for (int m = 0; m < 4; m++)
        #pragma unroll
        for (int n = 0; n < 4; n++)
            #pragma unroll
            for (int r = 0; r < 4; r++) acc[m][n][r] = 0.f;

    const uint32_t a_off = wm * 64 * P_PITCH + (lane & 15) * P_PITCH + (lane >> 4) * 16;
    const uint32_t b_off = P_B_OFF + (wn * 32 + (lane & 7) + ((lane >> 4) << 3)) * P_PITCH
                         + ((lane >> 3) & 1) * 16;

    #pragma unroll
    for (int ks = 0; ks < 6; ks++) {
        uint32_t af[4][4], bf[2][4];
        #pragma unroll
        for (int mt = 0; mt < 4; mt++)
            LDMATRIX_X4(af[mt], sb + a_off + mt * 16 * P_PITCH + ks * 32);
        #pragma unroll
        for (int ng = 0; ng < 2; ng++)
            LDMATRIX_X4(bf[ng], sb + b_off + ng * 16 * P_PITCH + ks * 32);
        #pragma unroll
        for (int mt = 0; mt < 4; mt++)
            #pragma unroll
            for (int ng = 0; ng < 2; ng++) {
                mma16816(acc[mt][2 * ng],     af[mt], bf[ng][0], bf[ng][1]);
                mma16816(acc[mt][2 * ng + 1], af[mt], bf[ng][2], bf[ng][3]);
            }
    }

    #pragma unroll
    for (int mt = 0; mt < 4; mt++) {
        int il = wm * 4 + mt;
        int t0 = lane >> 2;
        #pragma unroll
        for (int nt = 0; nt < 4; nt++) {
            int o = wn * 32 + nt * 8 + (lane & 3) * 2;
            float* p0 = out + (((size_t)b * Tc + t0)     * Nn + i0 + il) * FOUT + o;
            float* p1 = out + (((size_t)b * Tc + t0 + 8) * Nn + i0 + il) * FOUT + o;
            *(float2*)p0 = make_float2(fmaxf(acc[mt][nt][0], 0.f), fmaxf(acc[mt][nt][1], 0.f));
            *(float2*)p1 = make_float2(fmaxf(acc[mt][nt][2], 0.f), fmaxf(acc[mt][nt][3], 0.f));
        }
    }
}

// ---------------------------------------------------------------------------
extern "C" void kernel_launch(void* const* d_in, const int* in_sizes, int n_in,
                              void* d_out, int out_size) {
    const float* x     = (const float*)d_in[0];
    const float* sa    = (const float*)d_in[1];
    const float* cheb  = (const float*)d_in[2];
    const float* Theta = (const float*)d_in[3];
    float* out = (float*)d_out;

    cudaFuncSetAttribute(k_gemm_mma, cudaFuncAttributeMaxDynamicSharedMemorySize, GEMM_SMEM);
    cudaFuncSetAttribute(k_proj_mma, cudaFuncAttributeMaxDynamicSharedMemorySize, PROJ_SMEM);

    // 0) merged prep: att (4x thread parallelism), xT, ThT
    k_prep_all<<<PREP_GRID, 256>>>(cheb, sa, x, Theta);
    // 1) 24 GEMMs on tensor cores (1-term fp16, 2 CTAs/SM)
    dim3 grid(4, 8, Bc * Kc);
    k_gemm_mma<<<grid, 256, GEMM_SMEM>>>(0);
    // 2) tensor-core projection + relu
    dim3 pgrid(64, Bc);
    k_proj_mma<<<pgrid, 256, PROJ_SMEM>>>(out);
}

// round 16
// speedup vs baseline: 1.0148x; 1.0148x over previous
#include <cuda_runtime.h>
#include <cuda_fp16.h>
#include <cstdint>

// ---------------- problem constants ----------------
#define Bc 8
#define Tc 16
#define Nn 1024
#define FIN 32
#define FOUT 64
#define Kc 3
#define CC 512
#define NN (1024 * 1024)

// ---------------- scratch (no cudaMalloc allowed) ----------------
__device__ __half g_att[(size_t)Bc * Kc * NN];         // fp16(cheb*sa) [bk][i][j]  (50 MB)
__device__ __half g_xh[(size_t)Bc * CC * Nn];          // x^T fp16 [b][c][j]         (8 MB)
__device__ __half g_rhsh[(size_t)Bc * Kc * Nn * CC];   // fp16 rhs [bk][i][c]        (25 MB)
__device__ __half g_tht[FOUT * 96];                    // Theta^T fp16 [o][m]

// ---------------- helpers ----------------
__device__ __forceinline__ uint32_t smem_u32(const void* p) {
    uint32_t a;
    asm("{ .reg .u64 t; cvta.to.shared.u64 t, %1; cvt.u32.u64 %0, t; }" : "=r"(a) : "l"(p));
    return a;
}

__device__ __forceinline__ uint32_t pack2h(float a, float b) {
    __half ha = __float2half_rn(a);
    __half hb = __float2half_rn(b);
    return (uint32_t)__half_as_ushort(ha) | ((uint32_t)__half_as_ushort(hb) << 16);
}

__device__ __forceinline__ void mma16816(float* d, const uint32_t* a, uint32_t b0, uint32_t b1) {
    asm volatile(
        "mma.sync.aligned.m16n8k16.row.col.f32.f16.f16.f32 "
        "{%0,%1,%2,%3}, {%4,%5,%6,%7}, {%8,%9}, {%0,%1,%2,%3};"
        : "+f"(d[0]), "+f"(d[1]), "+f"(d[2]), "+f"(d[3])
        : "r"(a[0]), "r"(a[1]), "r"(a[2]), "r"(a[3]), "r"(b0), "r"(b1));
}

#define LDMATRIX_X4(r, addr) \
    asm volatile("ldmatrix.sync.aligned.m8n8.x4.shared.b16 {%0,%1,%2,%3}, [%4];" \
        : "=r"((r)[0]), "=r"((r)[1]), "=r"((r)[2]), "=r"((r)[3]) : "r"(addr))

#define CP_ASYNC16(dst_u32, src_ptr) \
    asm volatile("cp.async.cg.shared.global [%0], [%1], 16;" :: "r"(dst_u32), "l"(src_ptr))
#define CP_ASYNC_COMMIT() asm volatile("cp.async.commit_group;" ::: "memory")
#define CP_ASYNC_WAIT0()  asm volatile("cp.async.wait_group 0;" ::: "memory")
#define CP_ASYNC_WAIT1()  asm volatile("cp.async.wait_group 1;" ::: "memory")
#define CP_ASYNC_WAIT2()  asm volatile("cp.async.wait_group 2;" ::: "memory")

// ---------------------------------------------------------------------------
// Kernel 0 (merged prep) [exact R14 best]:
//   blocks [0, 512): att = fp16(cheb*sa); 8 positions x all 24 bk, batched ILP
//   blocks [512, 1536): x transpose -> xT fp16 [b, c=t*32+f, j]
//   block 1536: ThT[o][m] = fp16(Theta[m][o])
// ---------------------------------------------------------------------------
#define ATT_BLKS 512
#define X_BLKS   1024
#define PREP_GRID (ATT_BLKS + X_BLKS + 1)

__global__ __launch_bounds__(256)
void k_prep_all(const float* __restrict__ cheb, const float* __restrict__ sa,
                const float* __restrict__ x, const float* __restrict__ Theta) {
    __shared__ float tile[128][33];
    const int bid = blockIdx.x;
    const int tid = threadIdx.x;

    if (bid < ATT_BLKS) {
        const int pos = (bid * 256 + tid) * 8;
        float4 c0[3], c1[3];
        #pragma unroll
        for (int k = 0; k < 3; k++) {
            c0[k] = *(const float4*)(cheb + (size_t)k * NN + pos);
            c1[k] = *(const float4*)(cheb + (size_t)k * NN + pos + 4);
        }
        #pragma unroll
        for (int h = 0; h < 2; h++) {
            float4 s0[4], s1[4];
            #pragma unroll
            for (int q = 0; q < 4; q++) {
                int b = h * 4 + q;
                s0[q] = *(const float4*)(sa + (size_t)b * NN + pos);
                s1[q] = *(const float4*)(sa + (size_t)b * NN + pos + 4);
            }
            #pragma unroll
            for (int q = 0; q < 4; q++) {
                int b = h * 4 + q;
                #pragma unroll
                for (int k = 0; k < 3; k++) {
                    uint4 w;
                    w.x = pack2h(c0[k].x * s0[q].x, c0[k].y * s0[q].y);
                    w.y = pack2h(c0[k].z * s0[q].z, c0[k].w * s0[q].w);
                    w.z = pack2h(c1[k].x * s1[q].x, c1[k].y * s1[q].y);
                    w.w = pack2h(c1[k].z * s1[q].z, c1[k].w * s1[q].w);
                    *(uint4*)(g_att + (size_t)(b * 3 + k) * NN + pos) = w;
                }
            }
        }
    } else if (bid < ATT_BLKS + X_BLKS) {
        const int blk = bid - ATT_BLKS;
        const int jc = blk & 7;
        const int t  = (blk >> 3) & 15;
        const int b  = blk >> 7;
        const int j0 = jc * 128;

        const float* src = x + (((size_t)b * Tc + t) * Nn + j0) * FIN;
        #pragma unroll
        for (int e = 0; e < 4; e++) {
            int li = e * 256 + tid;
            int row = li >> 3, q = li & 7;
            float4 v = ((const float4*)src)[li];
            tile[row][q * 4 + 0] = v.x;
            tile[row][q * 4 + 1] = v.y;
            tile[row][q * 4 + 2] = v.z;
            tile[row][q * 4 + 3] = v.w;
        }
        __syncthreads();
        #pragma unroll
        for (int e = 0; e < 8; e++) {
            int li = e * 256 + tid;
            int f = li >> 6, jp = li & 63;
            int jj = jp * 2;
            uint32_t w = pack2h(tile[jj][f], tile[jj + 1][f]);
            size_t off = ((size_t)b * CC + t * FIN + f) * Nn + j0 + jj;
            *(uint32_t*)((char*)g_xh + off * 2) = w;
        }
    } else {
        for (int idx = tid; idx < 96 * FOUT; idx += 256) {
            int m = idx / FOUT, o = idx % FOUT;
            g_tht[o * 96 + m] = __float2half_rn(Theta[idx]);
        }
    }
}

// ---------------------------------------------------------------------------
// Kernel 1: GEMM [exact R8/R14]
// ---------------------------------------------------------------------------
#define BKg 64
#define NSTG 16
#define PITCH 144
#define OFF_A  0
#define A_SZ   (128 * PITCH)
#define OFF_B  A_SZ
#define B_SZ   (128 * PITCH)
#define STG_SZ (A_SZ + B_SZ)
#define GEMM_SMEM (2 * STG_SZ)          // 73728

__device__ __forceinline__ void cp_stage(uint32_t sstage, const __half* __restrict__ Ap,
                                         const __half* __restrict__ Bp, int j0, int tid) {
    #pragma unroll
    for (int e = 0; e < 4; e++) {
        int li = tid + e * 256;
        int row = li >> 3, q = li & 7;
        CP_ASYNC16(sstage + OFF_A + row * PITCH + q * 16,
                   (const char*)(Ap + (size_t)row * Nn + j0) + q * 16);
    }
    #pragma unroll
    for (int e = 0; e < 4; e++) {
        int li = tid + e * 256;
        int n = li >> 3, q = li & 7;
        CP_ASYNC16(sstage + OFF_B + n * PITCH + q * 16,
                   (const char*)(Bp + (size_t)n * Nn + j0) + q * 16);
    }
}

__global__ __launch_bounds__(256, 2)
void k_gemm_mma(int dummy) {
    extern __shared__ char smem[];
    const uint32_t sb = smem_u32(smem);
    const int tid = threadIdx.x;
    const int lane = tid & 31, wid = tid >> 5;
    const int wm = wid >> 2, wn = wid & 3;

    const int tile_c = blockIdx.x * 128;
    const int tile_i = blockIdx.y * 128;
    const int bk = blockIdx.z;
    const int b = bk / 3;

    const __half* Ap = g_att + (size_t)bk * NN + (size_t)tile_i * Nn;
    const __half* Bp = g_xh + ((size_t)b * CC + tile_c) * Nn;

    float acc[4][4][4];
    #pragma unroll
    for (int m = 0; m < 4; m++)
        #pragma unroll
        for (int n = 0; n < 4; n++)
            #pragma unroll
            for (int r = 0; r < 4; r++) acc[m][n][r] = 0.f;

    const uint32_t a_off = wm * 64 * PITCH + (lane & 15) * PITCH + (lane >> 4) * 16;
    const uint32_t b_off = (wn * 32 + (lane & 7) + ((lane >> 4) << 3)) * PITCH
                         + ((lane >> 3) & 1) * 16;

    cp_stage(sb, Ap, Bp, 0, tid);
    CP_ASYNC_COMMIT();

    #pragma unroll 1
    for (int s = 0; s < NSTG; s++) {
        const uint32_t sbs = sb + (s & 1) * STG_SZ;

        CP_ASYNC_WAIT0();
        __syncthreads();

        if (s + 1 < NSTG) {
            cp_stage(sb + ((s + 1) & 1) * STG_SZ, Ap, Bp, (s + 1) * BKg, tid);
            CP_ASYNC_COMMIT();
        }

        #pragma unroll
        for (int ks = 0; ks < 4; ks++) {
            uint32_t af[4][4], bf[2][4];
            #pragma unroll
            for (int mt = 0; mt < 4; mt++)
                LDMATRIX_X4(af[mt], sbs + OFF_A + a_off + mt * 16 * PITCH + ks * 32);
            #pragma unroll
            for (int ng = 0; ng < 2; ng++)
                LDMATRIX_X4(bf[ng], sbs + OFF_B + b_off + ng * 16 * PITCH + ks * 32);
            #pragma unroll
            for (int mt = 0; mt < 4; mt++)
                #pragma unroll
                for (int ng = 0; ng < 2; ng++) {
                    mma16816(acc[mt][2 * ng],     af[mt], bf[ng][0], bf[ng][1]);
                    mma16816(acc[mt][2 * ng + 1], af[mt], bf[ng][2], bf[ng][3]);
                }
        }
    }

    __half* Cb = g_rhsh + (size_t)bk * Nn * CC;
    #pragma unroll
    for (int mt = 0; mt < 4; mt++) {
        int r0 = tile_i + wm * 64 + mt * 16 + (lane >> 2);
        #pragma unroll
        for (int nt = 0; nt < 4; nt++) {
            int c0 = tile_c + wn * 32 + nt * 8 + (lane & 3) * 2;
            *(uint32_t*)(Cb + (size_t)r0 * CC + c0)       = pack2h(acc[mt][nt][0], acc[mt][nt][1]);
            *(uint32_t*)(Cb + (size_t)(r0 + 8) * CC + c0) = pack2h(acc[mt][nt][2], acc[mt][nt][3]);
        }
    }
}

// ---------------------------------------------------------------------------
// Kernel 2: tensor-core projection + ReLU, PIPELINED per-k loads
// CTA: 16 i x 16 t = 256 rows, K=96, N=64. 8 warps 4(M)x2(N).
// Loads split into 3 commit groups (k=0 + ThT, k=1, k=2); MMA consumes
// progressively with wait_group 2/1/0.
// ---------------------------------------------------------------------------
#define P_PITCH 208
#define P_A_SZ  (256 * P_PITCH)
#define P_B_OFF P_A_SZ
#define PROJ_SMEM (P_A_SZ + 64 * P_PITCH)   // 66560

__device__ __forceinline__ void proj_load_k(uint32_t sb, int b, int i0, int k, int tid) {
    // 1024 chunks of 16B for this k: il(16) x q(64); 4 per thread
    #pragma unroll
    for (int e = 0; e < 4; e++) {
        int li = tid + e * 256;
        int il = li >> 6, q = li & 63;
        int t = q >> 2, fq = q & 3;
        const char* src = (const char*)(g_rhsh + ((size_t)(b * 3 + k) * Nn + i0 + il) * CC) + q * 16;
        CP_ASYNC16(sb + (il * 16 + t) * P_PITCH + k * 64 + fq * 16, src);
    }
}

__global__ __launch_bounds__(256, 2)
void k_proj_mma(float* __restrict__ out) {
    extern __shared__ char smem[];
    const uint32_t sb = smem_u32(smem);
    const int tid = threadIdx.x;
    const int lane = tid & 31, wid = tid >> 5;
    const int wm = wid >> 1, wn = wid & 1;

    const int b  = blockIdx.y;
    const int i0 = blockIdx.x * 16;

    // group 0: k=0 + ThT
    proj_load_k(sb, b, i0, 0, tid);
    #pragma unroll
    for (int e = 0; e < 3; e++) {
        int li = tid + e * 256;
        int row = li / 12, q = li % 12;
        CP_ASYNC16(sb + P_B_OFF + row * P_PITCH + q * 16,
                   (const char*)(g_tht + row * 96) + q * 16);
    }
    CP_ASYNC_COMMIT();
    // group 1: k=1
    proj_load_k(sb, b, i0, 1, tid);
    CP_ASYNC_COMMIT();
    // group 2: k=2
    proj_load_k(sb, b, i0, 2, tid);
    CP_ASYNC_COMMIT();

    float acc[4][4][4];
    #pragma unroll
    for (int m = 0; m < 4; m++)
        #pragma unroll
        for (int n = 0; n < 4; n++)
            #pragma unroll
            for (int r = 0; r < 4; r++) acc[m][n][r] = 0.f;

    const uint32_t a_off = wm * 64 * P_PITCH + (lane & 15) * P_PITCH + (lane >> 4) * 16;
    const uint32_t b_off = P_B_OFF + (wn * 32 + (lane & 7) + ((lane >> 4) << 3)) * P_PITCH
                         + ((lane >> 3) & 1) * 16;

    #pragma unroll
    for (int k = 0; k < 3; k++) {
        if (k == 0) CP_ASYNC_WAIT2();
        else if (k == 1) CP_ASYNC_WAIT1();
        else CP_ASYNC_WAIT0();
        __syncthreads();

        #pragma unroll
        for (int kk = 0; kk < 2; kk++) {
            int ks = k * 2 + kk;
            uint32_t af[4][4], bf[2][4];
            #pragma unroll
            for (int mt = 0; mt < 4; mt++)
                LDMATRIX_X4(af[mt], sb + a_off + mt * 16 * P_PITCH + ks * 32);
            #pragma unroll
            for (int ng = 0; ng < 2; ng++)
                LDMATRIX_X4(bf[ng], sb + b_off + ng * 16 * P_PITCH + ks * 32);
            #pragma unroll
            for (int mt = 0; mt < 4; mt++)
                #pragma unroll
                for (int ng = 0; ng < 2; ng++) {
                    mma16816(acc[mt][2 * ng],     af[mt], bf[ng][0], bf[ng][1]);
                    mma16816(acc[mt][2 * ng + 1], af[mt], bf[ng][2], bf[ng][3]);
                }
        }
    }

    #pragma unroll
    for (int mt = 0; mt < 4; mt++) {
        int il = wm * 4 + mt;
        int t0 = lane >> 2;
        #pragma unroll
        for (int nt = 0; nt < 4; nt++) {
            int o = wn * 32 + nt * 8 + (lane & 3) * 2;
            float* p0 = out + (((size_t)b * Tc + t0)     * Nn + i0 + il) * FOUT + o;
            float* p1 = out + (((size_t)b * Tc + t0 + 8) * Nn + i0 + il) * FOUT + o;
            *(float2*)p0 = make_float2(fmaxf(acc[mt][nt][0], 0.f), fmaxf(acc[mt][nt][1], 0.f));
            *(float2*)p1 = make_float2(fmaxf(acc[mt][nt][2], 0.f), fmaxf(acc[mt][nt][3], 0.f));
        }
    }
}

// ---------------------------------------------------------------------------
extern "C" void kernel_launch(void* const* d_in, const int* in_sizes, int n_in,
                              void* d_out, int out_size) {
    const float* x     = (const float*)d_in[0];
    const float* sa    = (const float*)d_in[1];
    const float* cheb  = (const float*)d_in[2];
    const float* Theta = (const float*)d_in[3];
    float* out = (float*)d_out;

    cudaFuncSetAttribute(k_gemm_mma, cudaFuncAttributeMaxDynamicSharedMemorySize, GEMM_SMEM);
    cudaFuncSetAttribute(k_proj_mma, cudaFuncAttributeMaxDynamicSharedMemorySize, PROJ_SMEM);

    // 0) merged prep (R14 best): att, xT, ThT
    k_prep_all<<<PREP_GRID, 256>>>(cheb, sa, x, Theta);
    // 1) 24 GEMMs on tensor cores (1-term fp16, 2 CTAs/SM)
    dim3 grid(4, 8, Bc * Kc);
    k_gemm_mma<<<grid, 256, GEMM_SMEM>>>(0);
    // 2) tensor-core projection + relu (pipelined per-k loads)
    dim3 pgrid(64, Bc);
    k_proj_mma<<<pgrid, 256, PROJ_SMEM>>>(out);
}